// round 14
// baseline (speedup 1.0000x reference)
#include <cuda_runtime.h>
#include <cuda_fp16.h>
#include <cstdint>

#define NNODES_MAX 100000
#define NEDGES_MAX 2000000
#define NFEAT 128

// Scratch (allocation-free rule: __device__ globals; zero-initialized at load)
__device__ __half2 g_hh[(size_t)NNODES_MAX * (NFEAT / 2)];  // h = x@W (UNscaled), fp16
__device__ float g_dinv[NNODES_MAX];
__device__ int   g_cnt[NNODES_MAX];      // self-cleaned by k_gather each run
__device__ int   g_off[NNODES_MAX];
__device__ int   g_cursor[NNODES_MAX];
__device__ int   g_csr[NEDGES_MAX];
__device__ int   g_total;                // reset by k_gemm_count each run

// ---------------------------------------------------------------------------
// K1: fused GEMM + edge-count (+ g_total reset). Blocks [0, gemmBlocks) run the
// tensor-core GEMM h = x @ W; the rest grid-stride the dst-degree count.
#define XS_STRIDE 136
#define GEMM_SMEM (2 * 128 * XS_STRIDE * (int)sizeof(__half))

__global__ __launch_bounds__(256) void k_gemm_count(
        const float* __restrict__ X, const float* __restrict__ W, int M,
        const int* __restrict__ ei, int E, int gemmBlocks) {
    if (blockIdx.x >= gemmBlocks) {
        if (blockIdx.x == gemmBlocks && threadIdx.x == 0) g_total = 0;
        int nb = gridDim.x - gemmBlocks;
        int e4_total = E >> 2;
        for (int e4 = (blockIdx.x - gemmBlocks) * blockDim.x + threadIdx.x;
             e4 < e4_total; e4 += nb * blockDim.x) {
            int4 d = ((const int4*)(ei + E))[e4];
            atomicAdd(&g_cnt[d.x], 1);
            atomicAdd(&g_cnt[d.y], 1);
            atomicAdd(&g_cnt[d.z], 1);
            atomicAdd(&g_cnt[d.w], 1);
        }
        if (blockIdx.x == gemmBlocks) {
            int tail = E & 3;
            if ((int)threadIdx.x < tail)
                atomicAdd(&g_cnt[ei[E + (E & ~3) + threadIdx.x]], 1);
        }
        return;
    }

    // ---- GEMM body ----
    extern __shared__ __half smem[];
    __half* Xs = smem;                       // [128][136]
    __half* Wh = smem + 128 * XS_STRIDE;     // [128][136]

    int tid = threadIdx.x;
    int m0  = blockIdx.x * 128;

#pragma unroll
    for (int j = 0; j < 16; j++) {
        int idx = tid + j * 256;
        int r   = idx >> 5;
        int c4  = idx & 31;
        float4 v = make_float4(0.f, 0.f, 0.f, 0.f);
        int gr = m0 + r;
        if (gr < M)
            v = *(const float4*)(X + (size_t)gr * NFEAT + c4 * 4);
        __half2 h0 = __floats2half2_rn(v.x, v.y);
        __half2 h1 = __floats2half2_rn(v.z, v.w);
        uint2 u; u.x = *(unsigned*)&h0; u.y = *(unsigned*)&h1;
        *(uint2*)(Xs + r * XS_STRIDE + c4 * 4) = u;
    }
#pragma unroll
    for (int j = 0; j < 16; j++) {
        int idx = tid + j * 256;
        int r   = idx >> 5;
        int c4  = idx & 31;
        float4 v = *(const float4*)(W + (size_t)r * NFEAT + c4 * 4);
        __half2 h0 = __floats2half2_rn(v.x, v.y);
        __half2 h1 = __floats2half2_rn(v.z, v.w);
        uint2 u; u.x = *(unsigned*)&h0; u.y = *(unsigned*)&h1;
        *(uint2*)(Wh + r * XS_STRIDE + c4 * 4) = u;
    }
    __syncthreads();

    int lane = tid & 31;
    int wrp  = tid >> 5;
    int mrow = wrp * 16;

    float acc[16][4];
#pragma unroll
    for (int i = 0; i < 16; i++)
#pragma unroll
        for (int j = 0; j < 4; j++) acc[i][j] = 0.f;

    unsigned xs_base = (unsigned)__cvta_generic_to_shared(Xs);
    unsigned wh_base = (unsigned)__cvta_generic_to_shared(Wh);

#pragma unroll
    for (int kt = 0; kt < 8; kt++) {
        int k0 = kt * 16;
        unsigned a_addr = xs_base +
            (((mrow + (lane & 15)) * XS_STRIDE + k0 + (lane >> 4) * 8) << 1);
        unsigned a0, a1, a2, a3;
        asm volatile("ldmatrix.sync.aligned.m8n8.x4.shared.b16 {%0,%1,%2,%3}, [%4];"
                     : "=r"(a0), "=r"(a1), "=r"(a2), "=r"(a3) : "r"(a_addr));

#pragma unroll
        for (int nt2 = 0; nt2 < 8; nt2++) {
            int n0 = nt2 * 16;
            unsigned b_addr = wh_base +
                (((k0 + (lane & 15)) * XS_STRIDE + n0 + (lane >> 4) * 8) << 1);
            unsigned b0, b1, b2, b3;
            asm volatile("ldmatrix.sync.aligned.m8n8.x4.trans.shared.b16 {%0,%1,%2,%3}, [%4];"
                         : "=r"(b0), "=r"(b1), "=r"(b2), "=r"(b3) : "r"(b_addr));

            asm volatile("mma.sync.aligned.m16n8k16.row.col.f32.f16.f16.f32 "
                         "{%0,%1,%2,%3}, {%4,%5,%6,%7}, {%8,%9}, {%0,%1,%2,%3};"
                         : "+f"(acc[2 * nt2][0]), "+f"(acc[2 * nt2][1]),
                           "+f"(acc[2 * nt2][2]), "+f"(acc[2 * nt2][3])
                         : "r"(a0), "r"(a1), "r"(a2), "r"(a3), "r"(b0), "r"(b1));
            asm volatile("mma.sync.aligned.m16n8k16.row.col.f32.f16.f16.f32 "
                         "{%0,%1,%2,%3}, {%4,%5,%6,%7}, {%8,%9}, {%0,%1,%2,%3};"
                         : "+f"(acc[2 * nt2 + 1][0]), "+f"(acc[2 * nt2 + 1][1]),
                           "+f"(acc[2 * nt2 + 1][2]), "+f"(acc[2 * nt2 + 1][3])
                         : "r"(a0), "r"(a1), "r"(a2), "r"(a3), "r"(b2), "r"(b3));
        }
    }

    int g = lane >> 2, t = lane & 3;
    int r0 = m0 + mrow + g;
    int r1 = r0 + 8;
#pragma unroll
    for (int nt = 0; nt < 16; nt++) {
        if (r0 < M)
            g_hh[(size_t)r0 * (NFEAT / 2) + nt * 4 + t] =
                __floats2half2_rn(acc[nt][0], acc[nt][1]);
        if (r1 < M)
            g_hh[(size_t)r1 * (NFEAT / 2) + nt * 4 + t] =
                __floats2half2_rn(acc[nt][2], acc[nt][3]);
    }
}

// ---------------------------------------------------------------------------
// K2: offsets in ONE kernel — block-local shuffle scan + one atomicAdd per
// block on g_total for the base (offsets need not be in node order, only
// disjoint). Also writes cursor and dinv.
__global__ void k_offsets(int n) {
    __shared__ int ws[8];
    __shared__ int sbase;
    int t = threadIdx.x, lane = t & 31, wid = t >> 5;
    int i = blockIdx.x * 256 + t;
    int c = (i < n) ? g_cnt[i] : 0;
    int x = c;
#pragma unroll
    for (int ofs = 1; ofs < 32; ofs <<= 1) {
        int y = __shfl_up_sync(0xffffffffu, x, ofs);
        if (lane >= ofs) x += y;
    }
    if (lane == 31) ws[wid] = x;
    __syncthreads();
    if (wid == 0) {
        int y = (lane < 8) ? ws[lane] : 0;
#pragma unroll
        for (int ofs = 1; ofs < 8; ofs <<= 1) {
            int z = __shfl_up_sync(0xffffffffu, y, ofs);
            if (lane >= ofs) y += z;
        }
        if (lane < 8) ws[lane] = y;
    }
    __syncthreads();
    int incl = x + (wid > 0 ? ws[wid - 1] : 0);
    if (t == 255) sbase = atomicAdd(&g_total, incl);   // block total
    __syncthreads();
    if (i < n) {
        int off = sbase + incl - c;
        g_off[i] = off;
        g_cursor[i] = off;
        g_dinv[i] = rsqrtf((float)c + 1.0f);
    }
}

// ---------------------------------------------------------------------------
// K3: CSR fill
__global__ void k_csr4(const int* __restrict__ ei, int E) {
    int e4 = blockIdx.x * blockDim.x + threadIdx.x;
    if (e4 * 4 >= E) return;
    int4 s = ((const int4*)ei)[e4];
    int4 d = ((const int4*)(ei + E))[e4];
    g_csr[atomicAdd(&g_cursor[d.x], 1)] = s.x;
    g_csr[atomicAdd(&g_cursor[d.y], 1)] = s.y;
    g_csr[atomicAdd(&g_cursor[d.z], 1)] = s.z;
    g_csr[atomicAdd(&g_cursor[d.w], 1)] = s.w;
}
__global__ void k_csr1(const int* __restrict__ ei, int E) {
    int e = blockIdx.x * blockDim.x + threadIdx.x;
    if (e >= E) return;
    g_csr[atomicAdd(&g_cursor[ei[E + e]], 1)] = ei[e];
}

// ---------------------------------------------------------------------------
// K4: gather — one warp per dst node; self-cleans g_cnt for the next run.
// out = (sum_src dinv[s]*h[s] + dinv[node]*h[node]) * dinv[node] + b
__global__ __launch_bounds__(256) void k_gather(const float* __restrict__ b,
                                                float* __restrict__ out, int N) {
    int node = blockIdx.x * 8 + (threadIdx.x >> 5);
    if (node >= N) return;
    int lane = threadIdx.x & 31;

    int base = g_off[node];
    int cnt  = g_cnt[node];
    float dd = g_dinv[node];
    if (lane == 0) g_cnt[node] = 0;    // self-clean for next replay

    float4 acc;
    {
        uint2 u = ((const uint2*)(g_hh + (size_t)node * (NFEAT / 2)))[lane];
        float2 f0 = __half22float2(*(__half2*)&u.x);
        float2 f1 = __half22float2(*(__half2*)&u.y);
        acc = make_float4(f0.x * dd, f0.y * dd, f1.x * dd, f1.y * dd);
    }

    int i = 0;
    for (; i + 4 <= cnt; i += 4) {
        int s0 = g_csr[base + i];
        int s1 = g_csr[base + i + 1];
        int s2 = g_csr[base + i + 2];
        int s3 = g_csr[base + i + 3];
        float w0 = g_dinv[s0], w1 = g_dinv[s1], w2 = g_dinv[s2], w3 = g_dinv[s3];
        uint2 u0 = ((const uint2*)(g_hh + (size_t)s0 * (NFEAT / 2)))[lane];
        uint2 u1 = ((const uint2*)(g_hh + (size_t)s1 * (NFEAT / 2)))[lane];
        uint2 u2 = ((const uint2*)(g_hh + (size_t)s2 * (NFEAT / 2)))[lane];
        uint2 u3 = ((const uint2*)(g_hh + (size_t)s3 * (NFEAT / 2)))[lane];
        float2 a0 = __half22float2(*(__half2*)&u0.x), a1 = __half22float2(*(__half2*)&u0.y);
        float2 c0 = __half22float2(*(__half2*)&u1.x), c1 = __half22float2(*(__half2*)&u1.y);
        float2 d0 = __half22float2(*(__half2*)&u2.x), d1 = __half22float2(*(__half2*)&u2.y);
        float2 e0 = __half22float2(*(__half2*)&u3.x), e1 = __half22float2(*(__half2*)&u3.y);
        acc.x += a0.x * w0 + c0.x * w1 + d0.x * w2 + e0.x * w3;
        acc.y += a0.y * w0 + c0.y * w1 + d0.y * w2 + e0.y * w3;
        acc.z += a1.x * w0 + c1.x * w1 + d1.x * w2 + e1.x * w3;
        acc.w += a1.y * w0 + c1.y * w1 + d1.y * w2 + e1.y * w3;
    }
    for (; i < cnt; i++) {
        int s0 = g_csr[base + i];
        float w0 = g_dinv[s0];
        uint2 u0 = ((const uint2*)(g_hh + (size_t)s0 * (NFEAT / 2)))[lane];
        float2 a0 = __half22float2(*(__half2*)&u0.x), a1 = __half22float2(*(__half2*)&u0.y);
        acc.x += a0.x * w0; acc.y += a0.y * w0;
        acc.z += a1.x * w0; acc.w += a1.y * w0;
    }

    float4 bv = ((const float4*)b)[lane];
    float4 o;
    o.x = bv.x + acc.x * dd;
    o.y = bv.y + acc.y * dd;
    o.z = bv.z + acc.z * dd;
    o.w = bv.w + acc.w * dd;
    ((float4*)(out + (size_t)node * NFEAT))[lane] = o;
}

// ---------------------------------------------------------------------------
extern "C" void kernel_launch(void* const* d_in, const int* in_sizes, int n_in,
                              void* d_out, int out_size) {
    const float* x  = (const float*)d_in[0];
    const int*   ei = (const int*)d_in[1];
    const float* w  = (const float*)d_in[2];
    const float* b  = (const float*)d_in[3];
    float* out = (float*)d_out;

    int N = in_sizes[0] / NFEAT;
    int E = in_sizes[1] / 2;

    cudaFuncSetAttribute(k_gemm_count,
                         cudaFuncAttributeMaxDynamicSharedMemorySize, GEMM_SMEM);

    int gemmBlocks  = (N + 127) / 128;
    int countBlocks = 400;

    k_gemm_count<<<gemmBlocks + countBlocks, 256, GEMM_SMEM>>>(x, w, N, ei, E,
                                                               gemmBlocks);
    k_offsets<<<(N + 255) / 256, 256>>>(N);
    if ((E & 3) == 0)
        k_csr4<<<(E / 4 + 255) / 256, 256>>>(ei, E);
    else
        k_csr1<<<(E + 255) / 256, 256>>>(ei, E);
    k_gather<<<(N + 7) / 8, 256>>>(b, out, N);
}

// round 15
// speedup vs baseline: 2.6520x; 2.6520x over previous
#include <cuda_runtime.h>
#include <cuda_fp16.h>
#include <cstdint>

#define NNODES_MAX 100000
#define NEDGES_MAX 2000000
#define NFEAT 128

// Scratch (allocation-free rule: __device__ globals; zero-initialized at load)
__device__ __half2 g_hh[(size_t)NNODES_MAX * (NFEAT / 2)];  // h = x@W (UNscaled), fp16
__device__ float g_dinv[NNODES_MAX];
__device__ int   g_cnt[NNODES_MAX];
__device__ int   g_off[NNODES_MAX];
__device__ int   g_cursor[NNODES_MAX];
__device__ int   g_csr[NEDGES_MAX];
__device__ int   g_total;                // reset by k_gemm_count each run

// ---------------------------------------------------------------------------
__global__ void k_zero_cnt(int n) {
    int i = blockIdx.x * blockDim.x + threadIdx.x;
    if (i < n) g_cnt[i] = 0;
}

// ---------------------------------------------------------------------------
// K1: fused GEMM + edge-count (+ g_total reset). Blocks [0, gemmBlocks) run the
// tensor-core GEMM h = x @ W; the rest grid-stride the dst-degree count.
#define XS_STRIDE 136
#define GEMM_SMEM (2 * 128 * XS_STRIDE * (int)sizeof(__half))

__global__ __launch_bounds__(256) void k_gemm_count(
        const float* __restrict__ X, const float* __restrict__ W, int M,
        const int* __restrict__ ei, int E, int gemmBlocks) {
    if (blockIdx.x >= gemmBlocks) {
        if (blockIdx.x == gemmBlocks && threadIdx.x == 0) g_total = 0;
        int nb = gridDim.x - gemmBlocks;
        int e4_total = E >> 2;
        for (int e4 = (blockIdx.x - gemmBlocks) * blockDim.x + threadIdx.x;
             e4 < e4_total; e4 += nb * blockDim.x) {
            int4 d = ((const int4*)(ei + E))[e4];
            atomicAdd(&g_cnt[d.x], 1);
            atomicAdd(&g_cnt[d.y], 1);
            atomicAdd(&g_cnt[d.z], 1);
            atomicAdd(&g_cnt[d.w], 1);
        }
        if (blockIdx.x == gemmBlocks) {
            int tail = E & 3;
            if ((int)threadIdx.x < tail)
                atomicAdd(&g_cnt[ei[E + (E & ~3) + threadIdx.x]], 1);
        }
        return;
    }

    // ---- GEMM body ----
    extern __shared__ __half smem[];
    __half* Xs = smem;                       // [128][136]
    __half* Wh = smem + 128 * XS_STRIDE;     // [128][136]

    int tid = threadIdx.x;
    int m0  = blockIdx.x * 128;

#pragma unroll
    for (int j = 0; j < 16; j++) {
        int idx = tid + j * 256;
        int r   = idx >> 5;
        int c4  = idx & 31;
        float4 v = make_float4(0.f, 0.f, 0.f, 0.f);
        int gr = m0 + r;
        if (gr < M)
            v = *(const float4*)(X + (size_t)gr * NFEAT + c4 * 4);
        __half2 h0 = __floats2half2_rn(v.x, v.y);
        __half2 h1 = __floats2half2_rn(v.z, v.w);
        uint2 u; u.x = *(unsigned*)&h0; u.y = *(unsigned*)&h1;
        *(uint2*)(Xs + r * XS_STRIDE + c4 * 4) = u;
    }
#pragma unroll
    for (int j = 0; j < 16; j++) {
        int idx = tid + j * 256;
        int r   = idx >> 5;
        int c4  = idx & 31;
        float4 v = *(const float4*)(W + (size_t)r * NFEAT + c4 * 4);
        __half2 h0 = __floats2half2_rn(v.x, v.y);
        __half2 h1 = __floats2half2_rn(v.z, v.w);
        uint2 u; u.x = *(unsigned*)&h0; u.y = *(unsigned*)&h1;
        *(uint2*)(Wh + r * XS_STRIDE + c4 * 4) = u;
    }
    __syncthreads();

    int lane = tid & 31;
    int wrp  = tid >> 5;
    int mrow = wrp * 16;

    float acc[16][4];
#pragma unroll
    for (int i = 0; i < 16; i++)
#pragma unroll
        for (int j = 0; j < 4; j++) acc[i][j] = 0.f;

    unsigned xs_base = (unsigned)__cvta_generic_to_shared(Xs);
    unsigned wh_base = (unsigned)__cvta_generic_to_shared(Wh);

#pragma unroll
    for (int kt = 0; kt < 8; kt++) {
        int k0 = kt * 16;
        unsigned a_addr = xs_base +
            (((mrow + (lane & 15)) * XS_STRIDE + k0 + (lane >> 4) * 8) << 1);
        unsigned a0, a1, a2, a3;
        asm volatile("ldmatrix.sync.aligned.m8n8.x4.shared.b16 {%0,%1,%2,%3}, [%4];"
                     : "=r"(a0), "=r"(a1), "=r"(a2), "=r"(a3) : "r"(a_addr));

#pragma unroll
        for (int nt2 = 0; nt2 < 8; nt2++) {
            int n0 = nt2 * 16;
            unsigned b_addr = wh_base +
                (((k0 + (lane & 15)) * XS_STRIDE + n0 + (lane >> 4) * 8) << 1);
            unsigned b0, b1, b2, b3;
            asm volatile("ldmatrix.sync.aligned.m8n8.x4.trans.shared.b16 {%0,%1,%2,%3}, [%4];"
                         : "=r"(b0), "=r"(b1), "=r"(b2), "=r"(b3) : "r"(b_addr));

            asm volatile("mma.sync.aligned.m16n8k16.row.col.f32.f16.f16.f32 "
                         "{%0,%1,%2,%3}, {%4,%5,%6,%7}, {%8,%9}, {%0,%1,%2,%3};"
                         : "+f"(acc[2 * nt2][0]), "+f"(acc[2 * nt2][1]),
                           "+f"(acc[2 * nt2][2]), "+f"(acc[2 * nt2][3])
                         : "r"(a0), "r"(a1), "r"(a2), "r"(a3), "r"(b0), "r"(b1));
            asm volatile("mma.sync.aligned.m16n8k16.row.col.f32.f16.f16.f32 "
                         "{%0,%1,%2,%3}, {%4,%5,%6,%7}, {%8,%9}, {%0,%1,%2,%3};"
                         : "+f"(acc[2 * nt2 + 1][0]), "+f"(acc[2 * nt2 + 1][1]),
                           "+f"(acc[2 * nt2 + 1][2]), "+f"(acc[2 * nt2 + 1][3])
                         : "r"(a0), "r"(a1), "r"(a2), "r"(a3), "r"(b2), "r"(b3));
        }
    }

    int g = lane >> 2, t = lane & 3;
    int r0 = m0 + mrow + g;
    int r1 = r0 + 8;
#pragma unroll
    for (int nt = 0; nt < 16; nt++) {
        if (r0 < M)
            g_hh[(size_t)r0 * (NFEAT / 2) + nt * 4 + t] =
                __floats2half2_rn(acc[nt][0], acc[nt][1]);
        if (r1 < M)
            g_hh[(size_t)r1 * (NFEAT / 2) + nt * 4 + t] =
                __floats2half2_rn(acc[nt][2], acc[nt][3]);
    }
}

// ---------------------------------------------------------------------------
// K2: offsets in ONE kernel — block-local shuffle scan + one atomicAdd per
// block on g_total for the base (offsets need not be in node order, only
// disjoint). Also writes cursor and dinv.
__global__ void k_offsets(int n) {
    __shared__ int ws[8];
    __shared__ int sbase;
    int t = threadIdx.x, lane = t & 31, wid = t >> 5;
    int i = blockIdx.x * 256 + t;
    int c = (i < n) ? g_cnt[i] : 0;
    int x = c;
#pragma unroll
    for (int ofs = 1; ofs < 32; ofs <<= 1) {
        int y = __shfl_up_sync(0xffffffffu, x, ofs);
        if (lane >= ofs) x += y;
    }
    if (lane == 31) ws[wid] = x;
    __syncthreads();
    if (wid == 0) {
        int y = (lane < 8) ? ws[lane] : 0;
#pragma unroll
        for (int ofs = 1; ofs < 8; ofs <<= 1) {
            int z = __shfl_up_sync(0xffffffffu, y, ofs);
            if (lane >= ofs) y += z;
        }
        if (lane < 8) ws[lane] = y;
    }
    __syncthreads();
    int incl = x + (wid > 0 ? ws[wid - 1] : 0);
    if (t == 255) sbase = atomicAdd(&g_total, incl);   // block total
    __syncthreads();
    if (i < n) {
        int off = sbase + incl - c;
        g_off[i] = off;
        g_cursor[i] = off;
        g_dinv[i] = rsqrtf((float)c + 1.0f);
    }
}

// ---------------------------------------------------------------------------
// K3: CSR fill
__global__ void k_csr4(const int* __restrict__ ei, int E) {
    int e4 = blockIdx.x * blockDim.x + threadIdx.x;
    if (e4 * 4 >= E) return;
    int4 s = ((const int4*)ei)[e4];
    int4 d = ((const int4*)(ei + E))[e4];
    g_csr[atomicAdd(&g_cursor[d.x], 1)] = s.x;
    g_csr[atomicAdd(&g_cursor[d.y], 1)] = s.y;
    g_csr[atomicAdd(&g_cursor[d.z], 1)] = s.z;
    g_csr[atomicAdd(&g_cursor[d.w], 1)] = s.w;
}
__global__ void k_csr1(const int* __restrict__ ei, int E) {
    int e = blockIdx.x * blockDim.x + threadIdx.x;
    if (e >= E) return;
    g_csr[atomicAdd(&g_cursor[ei[E + e]], 1)] = ei[e];
}

// ---------------------------------------------------------------------------
// K4: gather — one warp per dst node (byte-identical to the proven R12 body;
// NO self-clean store — that correlated with a 4x latency serialization).
// out = (sum_src dinv[s]*h[s] + dinv[node]*h[node]) * dinv[node] + b
__global__ __launch_bounds__(256) void k_gather(const float* __restrict__ b,
                                                float* __restrict__ out, int N) {
    int node = blockIdx.x * 8 + (threadIdx.x >> 5);
    if (node >= N) return;
    int lane = threadIdx.x & 31;

    int base = g_off[node];
    int cnt  = g_cnt[node];
    float dd = g_dinv[node];

    float4 acc;
    {
        uint2 u = ((const uint2*)(g_hh + (size_t)node * (NFEAT / 2)))[lane];
        float2 f0 = __half22float2(*(__half2*)&u.x);
        float2 f1 = __half22float2(*(__half2*)&u.y);
        acc = make_float4(f0.x * dd, f0.y * dd, f1.x * dd, f1.y * dd);
    }

    int i = 0;
    for (; i + 4 <= cnt; i += 4) {
        int s0 = g_csr[base + i];
        int s1 = g_csr[base + i + 1];
        int s2 = g_csr[base + i + 2];
        int s3 = g_csr[base + i + 3];
        float w0 = g_dinv[s0], w1 = g_dinv[s1], w2 = g_dinv[s2], w3 = g_dinv[s3];
        uint2 u0 = ((const uint2*)(g_hh + (size_t)s0 * (NFEAT / 2)))[lane];
        uint2 u1 = ((const uint2*)(g_hh + (size_t)s1 * (NFEAT / 2)))[lane];
        uint2 u2 = ((const uint2*)(g_hh + (size_t)s2 * (NFEAT / 2)))[lane];
        uint2 u3 = ((const uint2*)(g_hh + (size_t)s3 * (NFEAT / 2)))[lane];
        float2 a0 = __half22float2(*(__half2*)&u0.x), a1 = __half22float2(*(__half2*)&u0.y);
        float2 c0 = __half22float2(*(__half2*)&u1.x), c1 = __half22float2(*(__half2*)&u1.y);
        float2 d0 = __half22float2(*(__half2*)&u2.x), d1 = __half22float2(*(__half2*)&u2.y);
        float2 e0 = __half22float2(*(__half2*)&u3.x), e1 = __half22float2(*(__half2*)&u3.y);
        acc.x += a0.x * w0 + c0.x * w1 + d0.x * w2 + e0.x * w3;
        acc.y += a0.y * w0 + c0.y * w1 + d0.y * w2 + e0.y * w3;
        acc.z += a1.x * w0 + c1.x * w1 + d1.x * w2 + e1.x * w3;
        acc.w += a1.y * w0 + c1.y * w1 + d1.y * w2 + e1.y * w3;
    }
    for (; i < cnt; i++) {
        int s0 = g_csr[base + i];
        float w0 = g_dinv[s0];
        uint2 u0 = ((const uint2*)(g_hh + (size_t)s0 * (NFEAT / 2)))[lane];
        float2 a0 = __half22float2(*(__half2*)&u0.x), a1 = __half22float2(*(__half2*)&u0.y);
        acc.x += a0.x * w0; acc.y += a0.y * w0;
        acc.z += a1.x * w0; acc.w += a1.y * w0;
    }

    float4 bv = ((const float4*)b)[lane];
    float4 o;
    o.x = bv.x + acc.x * dd;
    o.y = bv.y + acc.y * dd;
    o.z = bv.z + acc.z * dd;
    o.w = bv.w + acc.w * dd;
    ((float4*)(out + (size_t)node * NFEAT))[lane] = o;
}

// ---------------------------------------------------------------------------
extern "C" void kernel_launch(void* const* d_in, const int* in_sizes, int n_in,
                              void* d_out, int out_size) {
    const float* x  = (const float*)d_in[0];
    const int*   ei = (const int*)d_in[1];
    const float* w  = (const float*)d_in[2];
    const float* b  = (const float*)d_in[3];
    float* out = (float*)d_out;

    int N = in_sizes[0] / NFEAT;
    int E = in_sizes[1] / 2;

    cudaFuncSetAttribute(k_gemm_count,
                         cudaFuncAttributeMaxDynamicSharedMemorySize, GEMM_SMEM);

    int gemmBlocks  = (N + 127) / 128;
    int countBlocks = 400;

    k_zero_cnt<<<(N + 255) / 256, 256>>>(N);
    k_gemm_count<<<gemmBlocks + countBlocks, 256, GEMM_SMEM>>>(x, w, N, ei, E,
                                                               gemmBlocks);
    k_offsets<<<(N + 255) / 256, 256>>>(N);
    if ((E & 3) == 0)
        k_csr4<<<(E / 4 + 255) / 256, 256>>>(ei, E);
    else
        k_csr1<<<(E + 255) / 256, 256>>>(ei, E);
    k_gather<<<(N + 7) / 8, 256>>>(b, out, N);
}

// round 16
// speedup vs baseline: 2.6549x; 1.0011x over previous
#include <cuda_runtime.h>
#include <cuda_fp16.h>
#include <cstdint>

#define NNODES_MAX 100000
#define NEDGES_MAX 2000000
#define NFEAT 128

// Scratch (allocation-free rule: __device__ globals; zero-initialized at load)
__device__ __half2 g_hh[(size_t)NNODES_MAX * (NFEAT / 2)];  // h = x@W (UNscaled), fp16
__device__ float g_dinv[NNODES_MAX];
__device__ int   g_cnt[NNODES_MAX];
__device__ int   g_off[NNODES_MAX];
__device__ int   g_rank[NEDGES_MAX];     // per-edge rank among same-dst edges
__device__ int   g_csr[NEDGES_MAX];
__device__ int   g_total;                // reset by k_gemm_count each run

// ---------------------------------------------------------------------------
__global__ void k_zero_cnt(int n) {
    int i = blockIdx.x * blockDim.x + threadIdx.x;
    if (i < n) g_cnt[i] = 0;
}

// ---------------------------------------------------------------------------
// K1: fused GEMM + edge-count (+ g_total reset). Blocks [0, gemmBlocks) run the
// tensor-core GEMM h = x @ W; the rest grid-stride the dst-degree count AND
// record each edge's rank (the atomic's return value — previously discarded).
#define XS_STRIDE 136
#define GEMM_SMEM (2 * 128 * XS_STRIDE * (int)sizeof(__half))

__global__ __launch_bounds__(256) void k_gemm_count(
        const float* __restrict__ X, const float* __restrict__ W, int M,
        const int* __restrict__ ei, int E, int gemmBlocks) {
    if (blockIdx.x >= gemmBlocks) {
        if (blockIdx.x == gemmBlocks && threadIdx.x == 0) g_total = 0;
        int nb = gridDim.x - gemmBlocks;
        int e4_total = E >> 2;
        for (int e4 = (blockIdx.x - gemmBlocks) * blockDim.x + threadIdx.x;
             e4 < e4_total; e4 += nb * blockDim.x) {
            int4 d = ((const int4*)(ei + E))[e4];
            int4 r;
            r.x = atomicAdd(&g_cnt[d.x], 1);
            r.y = atomicAdd(&g_cnt[d.y], 1);
            r.z = atomicAdd(&g_cnt[d.z], 1);
            r.w = atomicAdd(&g_cnt[d.w], 1);
            ((int4*)g_rank)[e4] = r;
        }
        if (blockIdx.x == gemmBlocks) {
            int tail = E & 3;
            if ((int)threadIdx.x < tail) {
                int e = (E & ~3) + threadIdx.x;
                g_rank[e] = atomicAdd(&g_cnt[ei[E + e]], 1);
            }
        }
        return;
    }

    // ---- GEMM body ----
    extern __shared__ __half smem[];
    __half* Xs = smem;                       // [128][136]
    __half* Wh = smem + 128 * XS_STRIDE;     // [128][136]

    int tid = threadIdx.x;
    int m0  = blockIdx.x * 128;

#pragma unroll
    for (int j = 0; j < 16; j++) {
        int idx = tid + j * 256;
        int r   = idx >> 5;
        int c4  = idx & 31;
        float4 v = make_float4(0.f, 0.f, 0.f, 0.f);
        int gr = m0 + r;
        if (gr < M)
            v = *(const float4*)(X + (size_t)gr * NFEAT + c4 * 4);
        __half2 h0 = __floats2half2_rn(v.x, v.y);
        __half2 h1 = __floats2half2_rn(v.z, v.w);
        uint2 u; u.x = *(unsigned*)&h0; u.y = *(unsigned*)&h1;
        *(uint2*)(Xs + r * XS_STRIDE + c4 * 4) = u;
    }
#pragma unroll
    for (int j = 0; j < 16; j++) {
        int idx = tid + j * 256;
        int r   = idx >> 5;
        int c4  = idx & 31;
        float4 v = *(const float4*)(W + (size_t)r * NFEAT + c4 * 4);
        __half2 h0 = __floats2half2_rn(v.x, v.y);
        __half2 h1 = __floats2half2_rn(v.z, v.w);
        uint2 u; u.x = *(unsigned*)&h0; u.y = *(unsigned*)&h1;
        *(uint2*)(Wh + r * XS_STRIDE + c4 * 4) = u;
    }
    __syncthreads();

    int lane = tid & 31;
    int wrp  = tid >> 5;
    int mrow = wrp * 16;

    float acc[16][4];
#pragma unroll
    for (int i = 0; i < 16; i++)
#pragma unroll
        for (int j = 0; j < 4; j++) acc[i][j] = 0.f;

    unsigned xs_base = (unsigned)__cvta_generic_to_shared(Xs);
    unsigned wh_base = (unsigned)__cvta_generic_to_shared(Wh);

#pragma unroll
    for (int kt = 0; kt < 8; kt++) {
        int k0 = kt * 16;
        unsigned a_addr = xs_base +
            (((mrow + (lane & 15)) * XS_STRIDE + k0 + (lane >> 4) * 8) << 1);
        unsigned a0, a1, a2, a3;
        asm volatile("ldmatrix.sync.aligned.m8n8.x4.shared.b16 {%0,%1,%2,%3}, [%4];"
                     : "=r"(a0), "=r"(a1), "=r"(a2), "=r"(a3) : "r"(a_addr));

#pragma unroll
        for (int nt2 = 0; nt2 < 8; nt2++) {
            int n0 = nt2 * 16;
            unsigned b_addr = wh_base +
                (((k0 + (lane & 15)) * XS_STRIDE + n0 + (lane >> 4) * 8) << 1);
            unsigned b0, b1, b2, b3;
            asm volatile("ldmatrix.sync.aligned.m8n8.x4.trans.shared.b16 {%0,%1,%2,%3}, [%4];"
                         : "=r"(b0), "=r"(b1), "=r"(b2), "=r"(b3) : "r"(b_addr));

            asm volatile("mma.sync.aligned.m16n8k16.row.col.f32.f16.f16.f32 "
                         "{%0,%1,%2,%3}, {%4,%5,%6,%7}, {%8,%9}, {%0,%1,%2,%3};"
                         : "+f"(acc[2 * nt2][0]), "+f"(acc[2 * nt2][1]),
                           "+f"(acc[2 * nt2][2]), "+f"(acc[2 * nt2][3])
                         : "r"(a0), "r"(a1), "r"(a2), "r"(a3), "r"(b0), "r"(b1));
            asm volatile("mma.sync.aligned.m16n8k16.row.col.f32.f16.f16.f32 "
                         "{%0,%1,%2,%3}, {%4,%5,%6,%7}, {%8,%9}, {%0,%1,%2,%3};"
                         : "+f"(acc[2 * nt2 + 1][0]), "+f"(acc[2 * nt2 + 1][1]),
                           "+f"(acc[2 * nt2 + 1][2]), "+f"(acc[2 * nt2 + 1][3])
                         : "r"(a0), "r"(a1), "r"(a2), "r"(a3), "r"(b2), "r"(b3));
        }
    }

    int g = lane >> 2, t = lane & 3;
    int r0 = m0 + mrow + g;
    int r1 = r0 + 8;
#pragma unroll
    for (int nt = 0; nt < 16; nt++) {
        if (r0 < M)
            g_hh[(size_t)r0 * (NFEAT / 2) + nt * 4 + t] =
                __floats2half2_rn(acc[nt][0], acc[nt][1]);
        if (r1 < M)
            g_hh[(size_t)r1 * (NFEAT / 2) + nt * 4 + t] =
                __floats2half2_rn(acc[nt][2], acc[nt][3]);
    }
}

// ---------------------------------------------------------------------------
// K2: offsets — block-local shuffle scan + one atomicAdd per block on g_total
// (offsets need not be node-ordered, only disjoint). Also writes dinv.
__global__ void k_offsets(int n) {
    __shared__ int ws[8];
    __shared__ int sbase;
    int t = threadIdx.x, lane = t & 31, wid = t >> 5;
    int i = blockIdx.x * 256 + t;
    int c = (i < n) ? g_cnt[i] : 0;
    int x = c;
#pragma unroll
    for (int ofs = 1; ofs < 32; ofs <<= 1) {
        int y = __shfl_up_sync(0xffffffffu, x, ofs);
        if (lane >= ofs) x += y;
    }
    if (lane == 31) ws[wid] = x;
    __syncthreads();
    if (wid == 0) {
        int y = (lane < 8) ? ws[lane] : 0;
#pragma unroll
        for (int ofs = 1; ofs < 8; ofs <<= 1) {
            int z = __shfl_up_sync(0xffffffffu, y, ofs);
            if (lane >= ofs) y += z;
        }
        if (lane < 8) ws[lane] = y;
    }
    __syncthreads();
    int incl = x + (wid > 0 ? ws[wid - 1] : 0);
    if (t == 255) sbase = atomicAdd(&g_total, incl);   // block total
    __syncthreads();
    if (i < n) {
        g_off[i] = sbase + incl - c;
        g_dinv[i] = rsqrtf((float)c + 1.0f);
    }
}

// ---------------------------------------------------------------------------
// K3: CSR fill — ATOMIC-FREE: slot = off[dst] + rank[e] (rank captured during
// the count pass). Pure loads + one plain store per edge.
__global__ void k_csr4(const int* __restrict__ ei, int E) {
    int e4 = blockIdx.x * blockDim.x + threadIdx.x;
    if (e4 * 4 >= E) return;
    int4 s = ((const int4*)ei)[e4];
    int4 d = ((const int4*)(ei + E))[e4];
    int4 r = ((const int4*)g_rank)[e4];
    g_csr[g_off[d.x] + r.x] = s.x;
    g_csr[g_off[d.y] + r.y] = s.y;
    g_csr[g_off[d.z] + r.z] = s.z;
    g_csr[g_off[d.w] + r.w] = s.w;
}
__global__ void k_csr1(const int* __restrict__ ei, int E) {
    int e = blockIdx.x * blockDim.x + threadIdx.x;
    if (e >= E) return;
    g_csr[g_off[ei[E + e]] + g_rank[e]] = ei[e];
}

// ---------------------------------------------------------------------------
// K4: gather — one warp per dst node (proven R12/R15 body, unchanged).
// out = (sum_src dinv[s]*h[s] + dinv[node]*h[node]) * dinv[node] + b
__global__ __launch_bounds__(256) void k_gather(const float* __restrict__ b,
                                                float* __restrict__ out, int N) {
    int node = blockIdx.x * 8 + (threadIdx.x >> 5);
    if (node >= N) return;
    int lane = threadIdx.x & 31;

    int base = g_off[node];
    int cnt  = g_cnt[node];
    float dd = g_dinv[node];

    float4 acc;
    {
        uint2 u = ((const uint2*)(g_hh + (size_t)node * (NFEAT / 2)))[lane];
        float2 f0 = __half22float2(*(__half2*)&u.x);
        float2 f1 = __half22float2(*(__half2*)&u.y);
        acc = make_float4(f0.x * dd, f0.y * dd, f1.x * dd, f1.y * dd);
    }

    int i = 0;
    for (; i + 4 <= cnt; i += 4) {
        int s0 = g_csr[base + i];
        int s1 = g_csr[base + i + 1];
        int s2 = g_csr[base + i + 2];
        int s3 = g_csr[base + i + 3];
        float w0 = g_dinv[s0], w1 = g_dinv[s1], w2 = g_dinv[s2], w3 = g_dinv[s3];
        uint2 u0 = ((const uint2*)(g_hh + (size_t)s0 * (NFEAT / 2)))[lane];
        uint2 u1 = ((const uint2*)(g_hh + (size_t)s1 * (NFEAT / 2)))[lane];
        uint2 u2 = ((const uint2*)(g_hh + (size_t)s2 * (NFEAT / 2)))[lane];
        uint2 u3 = ((const uint2*)(g_hh + (size_t)s3 * (NFEAT / 2)))[lane];
        float2 a0 = __half22float2(*(__half2*)&u0.x), a1 = __half22float2(*(__half2*)&u0.y);
        float2 c0 = __half22float2(*(__half2*)&u1.x), c1 = __half22float2(*(__half2*)&u1.y);
        float2 d0 = __half22float2(*(__half2*)&u2.x), d1 = __half22float2(*(__half2*)&u2.y);
        float2 e0 = __half22float2(*(__half2*)&u3.x), e1 = __half22float2(*(__half2*)&u3.y);
        acc.x += a0.x * w0 + c0.x * w1 + d0.x * w2 + e0.x * w3;
        acc.y += a0.y * w0 + c0.y * w1 + d0.y * w2 + e0.y * w3;
        acc.z += a1.x * w0 + c1.x * w1 + d1.x * w2 + e1.x * w3;
        acc.w += a1.y * w0 + c1.y * w1 + d1.y * w2 + e1.y * w3;
    }
    for (; i < cnt; i++) {
        int s0 = g_csr[base + i];
        float w0 = g_dinv[s0];
        uint2 u0 = ((const uint2*)(g_hh + (size_t)s0 * (NFEAT / 2)))[lane];
        float2 a0 = __half22float2(*(__half2*)&u0.x), a1 = __half22float2(*(__half2*)&u0.y);
        acc.x += a0.x * w0; acc.y += a0.y * w0;
        acc.z += a1.x * w0; acc.w += a1.y * w0;
    }

    float4 bv = ((const float4*)b)[lane];
    float4 o;
    o.x = bv.x + acc.x * dd;
    o.y = bv.y + acc.y * dd;
    o.z = bv.z + acc.z * dd;
    o.w = bv.w + acc.w * dd;
    ((float4*)(out + (size_t)node * NFEAT))[lane] = o;
}

// ---------------------------------------------------------------------------
extern "C" void kernel_launch(void* const* d_in, const int* in_sizes, int n_in,
                              void* d_out, int out_size) {
    const float* x  = (const float*)d_in[0];
    const int*   ei = (const int*)d_in[1];
    const float* w  = (const float*)d_in[2];
    const float* b  = (const float*)d_in[3];
    float* out = (float*)d_out;

    int N = in_sizes[0] / NFEAT;
    int E = in_sizes[1] / 2;

    cudaFuncSetAttribute(k_gemm_count,
                         cudaFuncAttributeMaxDynamicSharedMemorySize, GEMM_SMEM);

    int gemmBlocks  = (N + 127) / 128;
    int countBlocks = 400;

    k_zero_cnt<<<(N + 255) / 256, 256>>>(N);
    k_gemm_count<<<gemmBlocks + countBlocks, 256, GEMM_SMEM>>>(x, w, N, ei, E,
                                                               gemmBlocks);
    k_offsets<<<(N + 255) / 256, 256>>>(N);
    if ((E & 3) == 0)
        k_csr4<<<(E / 4 + 255) / 256, 256>>>(ei, E);
    else
        k_csr1<<<(E + 255) / 256, 256>>>(ei, E);
    k_gather<<<(N + 7) / 8, 256>>>(b, out, N);
}

// round 17
// speedup vs baseline: 2.7460x; 1.0343x over previous
#include <cuda_runtime.h>
#include <cuda_fp16.h>
#include <cstdint>

#define NNODES_MAX 100000
#define NEDGES_MAX 2000000
#define NFEAT 128

// Scratch (allocation-free rule: __device__ globals; zero-initialized at load)
__device__ __half2 g_hh[(size_t)NNODES_MAX * (NFEAT / 2)];  // h = x@W (UNscaled), fp16
__device__ float g_dinv[NNODES_MAX];
__device__ int   g_cnt[NNODES_MAX];
__device__ int   g_off[NNODES_MAX];
__device__ int   g_rank[NEDGES_MAX];     // per-edge rank among same-dst edges
__device__ int   g_csr[NEDGES_MAX];
__device__ int   g_total;                // reset by k_gemm_count each run

// ---------------------------------------------------------------------------
__global__ void k_zero_cnt(int n) {
    int i = blockIdx.x * blockDim.x + threadIdx.x;
    if (i < n) g_cnt[i] = 0;
}

// ---------------------------------------------------------------------------
// K1: fused count + GEMM. COUNT blocks come FIRST (bid < countBlocks): they
// are smem-free and co-reside with GEMM blocks on the same SMs, so the count
// genuinely overlaps GEMM wave 1 (with count blocks last, dispatch order made
// the previous "fusion" run serially). Count records each edge's rank.
#define XS_STRIDE 136
#define GEMM_SMEM (2 * 128 * XS_STRIDE * (int)sizeof(__half))

__global__ __launch_bounds__(256) void k_gemm_count(
        const float* __restrict__ X, const float* __restrict__ W, int M,
        const int* __restrict__ ei, int E, int countBlocks) {
    if ((int)blockIdx.x < countBlocks) {
        if (blockIdx.x == 0 && threadIdx.x == 0) g_total = 0;
        int e4_total = E >> 2;
        for (int e4 = blockIdx.x * blockDim.x + threadIdx.x;
             e4 < e4_total; e4 += countBlocks * blockDim.x) {
            int4 d = ((const int4*)(ei + E))[e4];
            int4 r;
            r.x = atomicAdd(&g_cnt[d.x], 1);
            r.y = atomicAdd(&g_cnt[d.y], 1);
            r.z = atomicAdd(&g_cnt[d.z], 1);
            r.w = atomicAdd(&g_cnt[d.w], 1);
            ((int4*)g_rank)[e4] = r;
        }
        if (blockIdx.x == 0) {
            int tail = E & 3;
            if ((int)threadIdx.x < tail) {
                int e = (E & ~3) + threadIdx.x;
                g_rank[e] = atomicAdd(&g_cnt[ei[E + e]], 1);
            }
        }
        return;
    }

    // ---- GEMM body ----
    extern __shared__ __half smem[];
    __half* Xs = smem;                       // [128][136]
    __half* Wh = smem + 128 * XS_STRIDE;     // [128][136]

    int tid = threadIdx.x;
    int m0  = (blockIdx.x - countBlocks) * 128;

#pragma unroll
    for (int j = 0; j < 16; j++) {
        int idx = tid + j * 256;
        int r   = idx >> 5;
        int c4  = idx & 31;
        float4 v = make_float4(0.f, 0.f, 0.f, 0.f);
        int gr = m0 + r;
        if (gr < M)
            v = *(const float4*)(X + (size_t)gr * NFEAT + c4 * 4);
        __half2 h0 = __floats2half2_rn(v.x, v.y);
        __half2 h1 = __floats2half2_rn(v.z, v.w);
        uint2 u; u.x = *(unsigned*)&h0; u.y = *(unsigned*)&h1;
        *(uint2*)(Xs + r * XS_STRIDE + c4 * 4) = u;
    }
#pragma unroll
    for (int j = 0; j < 16; j++) {
        int idx = tid + j * 256;
        int r   = idx >> 5;
        int c4  = idx & 31;
        float4 v = *(const float4*)(W + (size_t)r * NFEAT + c4 * 4);
        __half2 h0 = __floats2half2_rn(v.x, v.y);
        __half2 h1 = __floats2half2_rn(v.z, v.w);
        uint2 u; u.x = *(unsigned*)&h0; u.y = *(unsigned*)&h1;
        *(uint2*)(Wh + r * XS_STRIDE + c4 * 4) = u;
    }
    __syncthreads();

    int lane = tid & 31;
    int wrp  = tid >> 5;
    int mrow = wrp * 16;

    float acc[16][4];
#pragma unroll
    for (int i = 0; i < 16; i++)
#pragma unroll
        for (int j = 0; j < 4; j++) acc[i][j] = 0.f;

    unsigned xs_base = (unsigned)__cvta_generic_to_shared(Xs);
    unsigned wh_base = (unsigned)__cvta_generic_to_shared(Wh);

#pragma unroll
    for (int kt = 0; kt < 8; kt++) {
        int k0 = kt * 16;
        unsigned a_addr = xs_base +
            (((mrow + (lane & 15)) * XS_STRIDE + k0 + (lane >> 4) * 8) << 1);
        unsigned a0, a1, a2, a3;
        asm volatile("ldmatrix.sync.aligned.m8n8.x4.shared.b16 {%0,%1,%2,%3}, [%4];"
                     : "=r"(a0), "=r"(a1), "=r"(a2), "=r"(a3) : "r"(a_addr));

#pragma unroll
        for (int nt2 = 0; nt2 < 8; nt2++) {
            int n0 = nt2 * 16;
            unsigned b_addr = wh_base +
                (((k0 + (lane & 15)) * XS_STRIDE + n0 + (lane >> 4) * 8) << 1);
            unsigned b0, b1, b2, b3;
            asm volatile("ldmatrix.sync.aligned.m8n8.x4.trans.shared.b16 {%0,%1,%2,%3}, [%4];"
                         : "=r"(b0), "=r"(b1), "=r"(b2), "=r"(b3) : "r"(b_addr));

            asm volatile("mma.sync.aligned.m16n8k16.row.col.f32.f16.f16.f32 "
                         "{%0,%1,%2,%3}, {%4,%5,%6,%7}, {%8,%9}, {%0,%1,%2,%3};"
                         : "+f"(acc[2 * nt2][0]), "+f"(acc[2 * nt2][1]),
                           "+f"(acc[2 * nt2][2]), "+f"(acc[2 * nt2][3])
                         : "r"(a0), "r"(a1), "r"(a2), "r"(a3), "r"(b0), "r"(b1));
            asm volatile("mma.sync.aligned.m16n8k16.row.col.f32.f16.f16.f32 "
                         "{%0,%1,%2,%3}, {%4,%5,%6,%7}, {%8,%9}, {%0,%1,%2,%3};"
                         : "+f"(acc[2 * nt2 + 1][0]), "+f"(acc[2 * nt2 + 1][1]),
                           "+f"(acc[2 * nt2 + 1][2]), "+f"(acc[2 * nt2 + 1][3])
                         : "r"(a0), "r"(a1), "r"(a2), "r"(a3), "r"(b2), "r"(b3));
        }
    }

    int g = lane >> 2, t = lane & 3;
    int r0 = m0 + mrow + g;
    int r1 = r0 + 8;
#pragma unroll
    for (int nt = 0; nt < 16; nt++) {
        if (r0 < M)
            g_hh[(size_t)r0 * (NFEAT / 2) + nt * 4 + t] =
                __floats2half2_rn(acc[nt][0], acc[nt][1]);
        if (r1 < M)
            g_hh[(size_t)r1 * (NFEAT / 2) + nt * 4 + t] =
                __floats2half2_rn(acc[nt][2], acc[nt][3]);
    }
}

// ---------------------------------------------------------------------------
// K2: offsets — block-local shuffle scan + one atomicAdd per block on g_total
// (offsets need not be node-ordered, only disjoint). Also writes dinv.
__global__ void k_offsets(int n) {
    __shared__ int ws[8];
    __shared__ int sbase;
    int t = threadIdx.x, lane = t & 31, wid = t >> 5;
    int i = blockIdx.x * 256 + t;
    int c = (i < n) ? g_cnt[i] : 0;
    int x = c;
#pragma unroll
    for (int ofs = 1; ofs < 32; ofs <<= 1) {
        int y = __shfl_up_sync(0xffffffffu, x, ofs);
        if (lane >= ofs) x += y;
    }
    if (lane == 31) ws[wid] = x;
    __syncthreads();
    if (wid == 0) {
        int y = (lane < 8) ? ws[lane] : 0;
#pragma unroll
        for (int ofs = 1; ofs < 8; ofs <<= 1) {
            int z = __shfl_up_sync(0xffffffffu, y, ofs);
            if (lane >= ofs) y += z;
        }
        if (lane < 8) ws[lane] = y;
    }
    __syncthreads();
    int incl = x + (wid > 0 ? ws[wid - 1] : 0);
    if (t == 255) sbase = atomicAdd(&g_total, incl);   // block total
    __syncthreads();
    if (i < n) {
        g_off[i] = sbase + incl - c;
        g_dinv[i] = rsqrtf((float)c + 1.0f);
    }
}

// ---------------------------------------------------------------------------
// K3: CSR fill — atomic-free, 8 edges/thread (MLP 8: all loads before stores).
__global__ void k_csr8(const int* __restrict__ ei, int E) {
    int e8 = blockIdx.x * blockDim.x + threadIdx.x;
    int e4_total = E >> 2;
    int e4a = 2 * e8;
    int e4b = 2 * e8 + 1;
    if (e4a >= e4_total) return;

    int4 sa = ((const int4*)ei)[e4a];
    int4 da = ((const int4*)(ei + E))[e4a];
    int4 ra = ((const int4*)g_rank)[e4a];
    bool hasB = (e4b < e4_total);
    int4 sb, db, rb;
    if (hasB) {
        sb = ((const int4*)ei)[e4b];
        db = ((const int4*)(ei + E))[e4b];
        rb = ((const int4*)g_rank)[e4b];
    }
    int oa0 = g_off[da.x], oa1 = g_off[da.y], oa2 = g_off[da.z], oa3 = g_off[da.w];
    int ob0 = 0, ob1 = 0, ob2 = 0, ob3 = 0;
    if (hasB) { ob0 = g_off[db.x]; ob1 = g_off[db.y]; ob2 = g_off[db.z]; ob3 = g_off[db.w]; }

    g_csr[oa0 + ra.x] = sa.x;
    g_csr[oa1 + ra.y] = sa.y;
    g_csr[oa2 + ra.z] = sa.z;
    g_csr[oa3 + ra.w] = sa.w;
    if (hasB) {
        g_csr[ob0 + rb.x] = sb.x;
        g_csr[ob1 + rb.y] = sb.y;
        g_csr[ob2 + rb.z] = sb.z;
        g_csr[ob3 + rb.w] = sb.w;
    }
}
__global__ void k_csr1(const int* __restrict__ ei, int E) {
    int e = blockIdx.x * blockDim.x + threadIdx.x;
    if (e >= E) return;
    g_csr[g_off[ei[E + e]] + g_rank[e]] = ei[e];
}

// ---------------------------------------------------------------------------
// K4: gather — one warp per dst node (proven R12/R15 body, unchanged).
// out = (sum_src dinv[s]*h[s] + dinv[node]*h[node]) * dinv[node] + b
__global__ __launch_bounds__(256) void k_gather(const float* __restrict__ b,
                                                float* __restrict__ out, int N) {
    int node = blockIdx.x * 8 + (threadIdx.x >> 5);
    if (node >= N) return;
    int lane = threadIdx.x & 31;

    int base = g_off[node];
    int cnt  = g_cnt[node];
    float dd = g_dinv[node];

    float4 acc;
    {
        uint2 u = ((const uint2*)(g_hh + (size_t)node * (NFEAT / 2)))[lane];
        float2 f0 = __half22float2(*(__half2*)&u.x);
        float2 f1 = __half22float2(*(__half2*)&u.y);
        acc = make_float4(f0.x * dd, f0.y * dd, f1.x * dd, f1.y * dd);
    }

    int i = 0;
    for (; i + 4 <= cnt; i += 4) {
        int s0 = g_csr[base + i];
        int s1 = g_csr[base + i + 1];
        int s2 = g_csr[base + i + 2];
        int s3 = g_csr[base + i + 3];
        float w0 = g_dinv[s0], w1 = g_dinv[s1], w2 = g_dinv[s2], w3 = g_dinv[s3];
        uint2 u0 = ((const uint2*)(g_hh + (size_t)s0 * (NFEAT / 2)))[lane];
        uint2 u1 = ((const uint2*)(g_hh + (size_t)s1 * (NFEAT / 2)))[lane];
        uint2 u2 = ((const uint2*)(g_hh + (size_t)s2 * (NFEAT / 2)))[lane];
        uint2 u3 = ((const uint2*)(g_hh + (size_t)s3 * (NFEAT / 2)))[lane];
        float2 a0 = __half22float2(*(__half2*)&u0.x), a1 = __half22float2(*(__half2*)&u0.y);
        float2 c0 = __half22float2(*(__half2*)&u1.x), c1 = __half22float2(*(__half2*)&u1.y);
        float2 d0 = __half22float2(*(__half2*)&u2.x), d1 = __half22float2(*(__half2*)&u2.y);
        float2 e0 = __half22float2(*(__half2*)&u3.x), e1 = __half22float2(*(__half2*)&u3.y);
        acc.x += a0.x * w0 + c0.x * w1 + d0.x * w2 + e0.x * w3;
        acc.y += a0.y * w0 + c0.y * w1 + d0.y * w2 + e0.y * w3;
        acc.z += a1.x * w0 + c1.x * w1 + d1.x * w2 + e1.x * w3;
        acc.w += a1.y * w0 + c1.y * w1 + d1.y * w2 + e1.y * w3;
    }
    for (; i < cnt; i++) {
        int s0 = g_csr[base + i];
        float w0 = g_dinv[s0];
        uint2 u0 = ((const uint2*)(g_hh + (size_t)s0 * (NFEAT / 2)))[lane];
        float2 a0 = __half22float2(*(__half2*)&u0.x), a1 = __half22float2(*(__half2*)&u0.y);
        acc.x += a0.x * w0; acc.y += a0.y * w0;
        acc.z += a1.x * w0; acc.w += a1.y * w0;
    }

    float4 bv = ((const float4*)b)[lane];
    float4 o;
    o.x = bv.x + acc.x * dd;
    o.y = bv.y + acc.y * dd;
    o.z = bv.z + acc.z * dd;
    o.w = bv.w + acc.w * dd;
    ((float4*)(out + (size_t)node * NFEAT))[lane] = o;
}

// ---------------------------------------------------------------------------
extern "C" void kernel_launch(void* const* d_in, const int* in_sizes, int n_in,
                              void* d_out, int out_size) {
    const float* x  = (const float*)d_in[0];
    const int*   ei = (const int*)d_in[1];
    const float* w  = (const float*)d_in[2];
    const float* b  = (const float*)d_in[3];
    float* out = (float*)d_out;

    int N = in_sizes[0] / NFEAT;
    int E = in_sizes[1] / 2;

    cudaFuncSetAttribute(k_gemm_count,
                         cudaFuncAttributeMaxDynamicSharedMemorySize, GEMM_SMEM);

    int gemmBlocks  = (N + 127) / 128;
    int countBlocks = 148;   // one per SM; co-resident with GEMM wave 1

    k_zero_cnt<<<(N + 255) / 256, 256>>>(N);
    k_gemm_count<<<countBlocks + gemmBlocks, 256, GEMM_SMEM>>>(x, w, N, ei, E,
                                                               countBlocks);
    k_offsets<<<(N + 255) / 256, 256>>>(N);
    if ((E & 3) == 0) {
        int e8_total = (E / 4 + 1) / 2;
        k_csr8<<<(e8_total + 255) / 256, 256>>>(ei, E);
    } else {
        k_csr1<<<(E + 255) / 256, 256>>>(ei, E);
    }
    k_gather<<<(N + 7) / 8, 256>>>(b, out, N);
}